// round 16
// baseline (speedup 1.0000x reference)
#include <cuda_runtime.h>
#include <cuda_fp16.h>
#include <cstdint>

// ---------------------------------------------------------------------------
// Problem constants
// ---------------------------------------------------------------------------
#define B_ROWS 4096
#define N_DIM  1024
#define P_DIM  32
#define E_DIM  16
#define C_DIM  (N_DIM * E_DIM)   /* 16384 output columns (i*16+e) */
#define KDIM   1024              /* single-term fp16 GEMM K */

// GEMM tiling: CTA 128x128, 8 warps (32x64 each, 4Mx2N), 2 CTAs/SM.
#define BM 128
#define BN 128
#define BK 64                        /* fp16 elems per K-chunk (128B rows) */
#define NCH (KDIM / BK)              /* 16 */
#define NSTAGES 3
#define STAGE_A_BYTES (BM * 128)     /* 16 KB */
#define STAGE_B_BYTES (BN * 128)     /* 16 KB */
#define STAGE_BYTES (STAGE_A_BYTES + STAGE_B_BYTES)   /* 32 KB */
#define SMEM_DYN (NSTAGES * STAGE_BYTES)              /* 96 KB -> 2 CTAs/SM */
#define NTHREADS 256

// Prologue: 2048 filter blocks (2 per i-row, 512 j each) + 4096 convert rows.
#define FILT_BLOCKS 2048
#define CONV_BLOCKS ((B_ROWS * N_DIM) / (256 * 4))    /* 4096 */

// ---------------------------------------------------------------------------
// Device scratch (allocation-free rule: __device__ globals)
// ---------------------------------------------------------------------------
__device__ __align__(16) __half g_A[(size_t)B_ROWS * KDIM];   // 8 MB
__device__ __align__(16) __half g_Bm[(size_t)C_DIM * KDIM];   // 32 MB

// ---------------------------------------------------------------------------
// PTX helpers (baseline features only — must compile for compute_103)
// ---------------------------------------------------------------------------
__device__ __forceinline__ uint32_t cvta_shared(const void* p) {
    return (uint32_t)__cvta_generic_to_shared(p);
}

__device__ __forceinline__ void cp_async16(uint32_t dst, const void* src) {
    asm volatile("cp.async.cg.shared.global [%0], [%1], 16;\n"
                 :: "r"(dst), "l"(src) : "memory");
}

__device__ __forceinline__ void ldmatrix_x4(uint32_t* d, uint32_t addr) {
    asm volatile("ldmatrix.sync.aligned.m8n8.x4.shared.b16 {%0,%1,%2,%3}, [%4];"
                 : "=r"(d[0]), "=r"(d[1]), "=r"(d[2]), "=r"(d[3]) : "r"(addr));
}

__device__ __forceinline__ void mma_f16(float* c, const uint32_t* a,
                                        uint32_t b0, uint32_t b1) {
    asm volatile("mma.sync.aligned.m16n8k16.row.col.f32.f16.f16.f32 "
                 "{%0,%1,%2,%3}, {%4,%5,%6,%7}, {%8,%9}, {%0,%1,%2,%3};"
                 : "+f"(c[0]), "+f"(c[1]), "+f"(c[2]), "+f"(c[3])
                 : "r"(a[0]), "r"(a[1]), "r"(a[2]), "r"(a[3]),
                   "r"(b0), "r"(b1));
}

__device__ __forceinline__ uint32_t sw128(uint32_t off) {
    return off ^ ((off >> 3) & 0x70);
}

// Packed fp32x2 FMA (Blackwell FFMA2; sm_100+ PTX, non-'a' feature)
__device__ __forceinline__ uint64_t fma_f32x2(uint64_t a, uint64_t b, uint64_t c) {
    uint64_t d;
    asm("fma.rn.f32x2 %0, %1, %2, %3;" : "=l"(d) : "l"(a), "l"(b), "l"(c));
    return d;
}
__device__ __forceinline__ uint64_t pack_f32x2(float lo, float hi) {
    uint64_t d;
    asm("mov.b64 %0, {%1, %2};" : "=l"(d) : "f"(lo), "f"(hi));
    return d;
}
__device__ __forceinline__ void unpack_f32x2(float& lo, float& hi, uint64_t v) {
    asm("mov.b64 {%0, %1}, %2;" : "=f"(lo), "=f"(hi) : "l"(v));
}

// PDL device hooks (sm_90-baseline griddepcontrol, not arch-'a'-gated)
__device__ __forceinline__ void pdl_trigger() {
    asm volatile("griddepcontrol.launch_dependents;");
}
__device__ __forceinline__ void pdl_wait() {
    asm volatile("griddepcontrol.wait;" ::: "memory");
}

// ---------------------------------------------------------------------------
// Kernel 1 (fused prologue):
//   blocks [0, FILT_BLOCKS): filter half-row — i = bid>>1, j-half = (bid&1)*512,
//       2 j per thread (float2 loads pack directly into f32x2 operands).
//       Halved per-thread regs/work vs R12 -> ~2x blocks/SM, shorter critical
//       path, T-stream closer to DRAM floor.
//   blocks [FILT_BLOCKS, ..): convert one x row (unchanged).
// ---------------------------------------------------------------------------
__global__ void __launch_bounds__(256)
prologue_kernel(const float* __restrict__ x,
                const float* __restrict__ params,
                const float* __restrict__ T) {
    if (blockIdx.x >= FILT_BLOCKS) {
        // ---- convert x ----
        int t = (blockIdx.x - FILT_BLOCKS) * blockDim.x + threadIdx.x;
        int idx4 = t << 2;
        float4 v = *reinterpret_cast<const float4*>(x + idx4);
        ushort4 hv;
        hv.x = __half_as_ushort(__float2half_rn(v.x));
        hv.y = __half_as_ushort(__float2half_rn(v.y));
        hv.z = __half_as_ushort(__float2half_rn(v.z));
        hv.w = __half_as_ushort(__float2half_rn(v.w));
        *reinterpret_cast<ushort4*>(g_A + idx4) = hv;
        pdl_trigger();
        return;
    }

    // ---- build filters: half-row unit ----
    __shared__ __align__(8) uint64_t sp2[P_DIM * E_DIM];   // {w,w} packed
    for (int s = threadIdx.x; s < P_DIM * E_DIM; s += blockDim.x) {
        float w = params[s];
        sp2[s] = pack_f32x2(w, w);
    }
    __syncthreads();

    const int i  = blockIdx.x >> 1;                         // 0..1023
    const int j0 = ((blockIdx.x & 1) << 9) + (threadIdx.x << 1);  // 2 j per thread
    const size_t tbase = ((size_t)i << 10) + j0;

    uint64_t acc[E_DIM];
    const uint64_t z = pack_f32x2(0.0f, 0.0f);
#pragma unroll
    for (int e = 0; e < E_DIM; e++) acc[e] = z;

#pragma unroll
    for (int p0 = 0; p0 < P_DIM; p0 += 4) {
        // 4 independent 8B loads in flight; each is directly one f32x2 operand
        float2 v0 = *reinterpret_cast<const float2*>(T + ((size_t)(p0+0) << 20) + tbase);
        float2 v1 = *reinterpret_cast<const float2*>(T + ((size_t)(p0+1) << 20) + tbase);
        float2 v2 = *reinterpret_cast<const float2*>(T + ((size_t)(p0+2) << 20) + tbase);
        float2 v3 = *reinterpret_cast<const float2*>(T + ((size_t)(p0+3) << 20) + tbase);
        uint64_t t0 = pack_f32x2(v0.x, v0.y);
        uint64_t t1 = pack_f32x2(v1.x, v1.y);
        uint64_t t2 = pack_f32x2(v2.x, v2.y);
        uint64_t t3 = pack_f32x2(v3.x, v3.y);
#pragma unroll
        for (int e = 0; e < E_DIM; e++) {
            acc[e] = fma_f32x2(t0, sp2[(p0+0) * E_DIM + e], acc[e]);
            acc[e] = fma_f32x2(t1, sp2[(p0+1) * E_DIM + e], acc[e]);
            acc[e] = fma_f32x2(t2, sp2[(p0+2) * E_DIM + e], acc[e]);
            acc[e] = fma_f32x2(t3, sp2[(p0+3) * E_DIM + e], acc[e]);
        }
    }

#pragma unroll
    for (int e = 0; e < E_DIM; e++) {
        int c = i * E_DIM + e;
        float a0, a1;
        unpack_f32x2(a0, a1, acc[e]);
        ushort2 hv;
        hv.x = __half_as_ushort(__float2half_rn(a0));
        hv.y = __half_as_ushort(__float2half_rn(a1));
        *reinterpret_cast<ushort2*>(g_Bm + (size_t)c * KDIM + j0) = hv;
    }
    pdl_trigger();
}

// ---------------------------------------------------------------------------
// Kernel 2: GEMM out[b,c] = sum_k A[b,k]*W[c,k], swish, fp32 out.
// CTA 128x128, 8 warps (4Mx2N, 32x64 each), 3-stage cp.async pipeline,
// 2 CTAs/SM.  Byte-identical mainloop to the proven 332us version + PDL wait.
// ---------------------------------------------------------------------------
__device__ __forceinline__ void load_chunk(uint32_t sbase, int tid, int kc,
                                           const __half* __restrict__ Ag,
                                           const __half* __restrict__ Bg) {
    int st = kc % NSTAGES;
    uint32_t stA = sbase + st * STAGE_BYTES;
    uint32_t stB = stA + STAGE_A_BYTES;
    const __half* ga = Ag + kc * BK;
    const __half* gb = Bg + kc * BK;
#pragma unroll
    for (int i = 0; i < 4; i++) {               // A: 128 rows x 8 vec16
        int v = i * NTHREADS + tid;
        int row = v >> 3, c16 = v & 7;
        uint32_t off = (uint32_t)(row * 128 + c16 * 16);
        cp_async16(stA + sw128(off), ga + (size_t)row * KDIM + (c16 << 3));
    }
#pragma unroll
    for (int i = 0; i < 4; i++) {               // B: 128 rows x 8 vec16
        int v = i * NTHREADS + tid;
        int row = v >> 3, c16 = v & 7;
        uint32_t off = (uint32_t)(row * 128 + c16 * 16);
        cp_async16(stB + sw128(off), gb + (size_t)row * KDIM + (c16 << 3));
    }
    asm volatile("cp.async.commit_group;\n" ::: "memory");
}

__global__ void __launch_bounds__(NTHREADS, 2)
gemm_swish_kernel(float* __restrict__ out) {
    extern __shared__ char dsm[];
    const int tid  = threadIdx.x;
    const int wid  = tid >> 5;
    const int lane = tid & 31;
    const int warp_m = wid & 3;     // 0..3 -> 32-row slices
    const int warp_n = wid >> 2;    // 0..1 -> 64-col slices

    uint32_t sbase = cvta_shared(dsm);

    const size_t m_base = (size_t)blockIdx.x * BM;
    const size_t n_base = (size_t)blockIdx.y * BN;
    const __half* __restrict__ Ag = g_A  + m_base * KDIM;
    const __half* __restrict__ Bg = g_Bm + n_base * KDIM;

    float acc[2][8][4];
#pragma unroll
    for (int mi = 0; mi < 2; mi++)
#pragma unroll
        for (int ni = 0; ni < 8; ni++)
#pragma unroll
            for (int c = 0; c < 4; c++) acc[mi][ni][c] = 0.0f;

    // PDL: prologue grid must be complete before reading g_A/g_Bm.
    pdl_wait();

    // prologue: stages 0,1 in flight
    load_chunk(sbase, tid, 0, Ag, Bg);
    load_chunk(sbase, tid, 1, Ag, Bg);

    // per-lane ldmatrix row offsets
    const int a_row = warp_m * 32 + (lane & 15);                      // + mi*16
    const int a_kh  = (lane >> 4) << 4;                               // 0/16 B
    const int b_row = warp_n * 64 + (lane & 7) + ((lane & 16) >> 1);  // + ni*16
    const int b_kh  = (lane & 8) << 1;                                // 0/16 B

    for (int k = 0; k < NCH; k++) {
        if (k < NCH - 1) asm volatile("cp.async.wait_group 1;\n" ::: "memory");
        else             asm volatile("cp.async.wait_group 0;\n" ::: "memory");
        __syncthreads();

        if (k + 2 < NCH) load_chunk(sbase, tid, k + 2, Ag, Bg);

        int st = k % NSTAGES;
        uint32_t stA = sbase + st * STAGE_BYTES;
        uint32_t stB = stA + STAGE_A_BYTES;

#pragma unroll
        for (int kk = 0; kk < 4; kk++) {        // 4 x k16 per 64-chunk
            uint32_t b[4][4];
#pragma unroll
            for (int ni = 0; ni < 4; ni++) {
                uint32_t off = (uint32_t)((b_row + ni * 16) * 128 + kk * 32 + b_kh);
                ldmatrix_x4(b[ni], stB + sw128(off));
            }
            uint32_t a[2][4];
#pragma unroll
            for (int mi = 0; mi < 2; mi++) {
                uint32_t off = (uint32_t)((a_row + mi * 16) * 128 + kk * 32 + a_kh);
                ldmatrix_x4(a[mi], stA + sw128(off));
            }
#pragma unroll
            for (int mi = 0; mi < 2; mi++)
#pragma unroll
                for (int n8 = 0; n8 < 8; n8++)
                    mma_f16(acc[mi][n8], a[mi],
                            b[n8 >> 1][(n8 & 1) * 2],
                            b[n8 >> 1][(n8 & 1) * 2 + 1]);
        }
    }

    // epilogue: swish + store fp32
    const int quad = lane >> 2;        // 0..7: row within 8-row group
    const int tcol = (lane & 3) * 2;   // col pair
#pragma unroll
    for (int mi = 0; mi < 2; mi++) {
        size_t row0 = m_base + warp_m * 32 + mi * 16 + quad;
#pragma unroll
        for (int n8 = 0; n8 < 8; n8++) {
            size_t col = n_base + warp_n * 64 + n8 * 8 + tcol;
            float a0 = acc[mi][n8][0], a1 = acc[mi][n8][1];
            float a2 = acc[mi][n8][2], a3 = acc[mi][n8][3];
            float2 v0, v1;
            v0.x = a0 / (1.0f + __expf(-a0));
            v0.y = a1 / (1.0f + __expf(-a1));
            v1.x = a2 / (1.0f + __expf(-a2));
            v1.y = a3 / (1.0f + __expf(-a3));
            *reinterpret_cast<float2*>(out + row0 * C_DIM + col)       = v0;
            *reinterpret_cast<float2*>(out + (row0 + 8) * C_DIM + col) = v1;
        }
    }
}

// ---------------------------------------------------------------------------
// Launch: prologue, then GEMM with PDL (programmatic stream serialization)
// ---------------------------------------------------------------------------
extern "C" void kernel_launch(void* const* d_in, const int* in_sizes, int n_in,
                              void* d_out, int out_size) {
    const float* x = nullptr;
    const float* params = nullptr;
    const float* T = nullptr;
    for (int i = 0; i < n_in; i++) {
        if (in_sizes[i] == B_ROWS * N_DIM)             x      = (const float*)d_in[i];
        else if (in_sizes[i] == P_DIM * E_DIM)         params = (const float*)d_in[i];
        else if (in_sizes[i] == P_DIM * N_DIM * N_DIM) T      = (const float*)d_in[i];
    }
    float* out = (float*)d_out;

    prologue_kernel<<<FILT_BLOCKS + CONV_BLOCKS, 256>>>(x, params, T);

    cudaFuncSetAttribute(gemm_swish_kernel,
                         cudaFuncAttributeMaxDynamicSharedMemorySize, SMEM_DYN);

    cudaLaunchConfig_t cfg = {};
    cfg.gridDim = dim3(B_ROWS / BM, C_DIM / BN);
    cfg.blockDim = dim3(NTHREADS);
    cfg.dynamicSmemBytes = SMEM_DYN;
    cfg.stream = 0;
    cudaLaunchAttribute attrs[1];
    attrs[0].id = cudaLaunchAttributeProgrammaticStreamSerialization;
    attrs[0].val.programmaticStreamSerializationAllowed = 1;
    cfg.attrs = attrs;
    cfg.numAttrs = 1;
    cudaLaunchKernelEx(&cfg, gemm_swish_kernel, out);
}

// round 17
// speedup vs baseline: 1.0258x; 1.0258x over previous
#include <cuda_runtime.h>
#include <cuda_fp16.h>
#include <cstdint>

// ---------------------------------------------------------------------------
// Problem constants
// ---------------------------------------------------------------------------
#define B_ROWS 4096
#define N_DIM  1024
#define P_DIM  32
#define E_DIM  16
#define C_DIM  (N_DIM * E_DIM)   /* 16384 output columns (i*16+e) */
#define KDIM   1024              /* single-term fp16 GEMM K */

// GEMM tiling: CTA 128x128, 8 warps (32x64 each, 4Mx2N), 2 CTAs/SM.
#define BM 128
#define BN 128
#define BK 64                        /* fp16 elems per K-chunk (128B rows) */
#define NCH (KDIM / BK)              /* 16 */
#define NSTAGES 3
#define STAGE_A_BYTES (BM * 128)     /* 16 KB */
#define STAGE_B_BYTES (BN * 128)     /* 16 KB */
#define STAGE_BYTES (STAGE_A_BYTES + STAGE_B_BYTES)   /* 32 KB */
#define SMEM_DYN (NSTAGES * STAGE_BYTES)              /* 96 KB -> 2 CTAs/SM */
#define NTHREADS 256

// Prologue: 1024 filter blocks (R12-exact) + 1024 convert blocks
// (4 rows each, 4 independent float4 loads per thread -> MLP 4).
#define FILT_BLOCKS 1024
#define CONV_BLOCKS 1024

// ---------------------------------------------------------------------------
// Device scratch (allocation-free rule: __device__ globals)
// ---------------------------------------------------------------------------
__device__ __align__(16) __half g_A[(size_t)B_ROWS * KDIM];   // 8 MB
__device__ __align__(16) __half g_Bm[(size_t)C_DIM * KDIM];   // 32 MB

// ---------------------------------------------------------------------------
// PTX helpers (baseline features only — must compile for compute_103)
// ---------------------------------------------------------------------------
__device__ __forceinline__ uint32_t cvta_shared(const void* p) {
    return (uint32_t)__cvta_generic_to_shared(p);
}

__device__ __forceinline__ void cp_async16(uint32_t dst, const void* src) {
    asm volatile("cp.async.cg.shared.global [%0], [%1], 16;\n"
                 :: "r"(dst), "l"(src) : "memory");
}

__device__ __forceinline__ void ldmatrix_x4(uint32_t* d, uint32_t addr) {
    asm volatile("ldmatrix.sync.aligned.m8n8.x4.shared.b16 {%0,%1,%2,%3}, [%4];"
                 : "=r"(d[0]), "=r"(d[1]), "=r"(d[2]), "=r"(d[3]) : "r"(addr));
}

__device__ __forceinline__ void mma_f16(float* c, const uint32_t* a,
                                        uint32_t b0, uint32_t b1) {
    asm volatile("mma.sync.aligned.m16n8k16.row.col.f32.f16.f16.f32 "
                 "{%0,%1,%2,%3}, {%4,%5,%6,%7}, {%8,%9}, {%0,%1,%2,%3};"
                 : "+f"(c[0]), "+f"(c[1]), "+f"(c[2]), "+f"(c[3])
                 : "r"(a[0]), "r"(a[1]), "r"(a[2]), "r"(a[3]),
                   "r"(b0), "r"(b1));
}

__device__ __forceinline__ uint32_t sw128(uint32_t off) {
    return off ^ ((off >> 3) & 0x70);
}

// Packed fp32x2 FMA (Blackwell FFMA2; sm_100+ PTX, non-'a' feature)
__device__ __forceinline__ uint64_t fma_f32x2(uint64_t a, uint64_t b, uint64_t c) {
    uint64_t d;
    asm("fma.rn.f32x2 %0, %1, %2, %3;" : "=l"(d) : "l"(a), "l"(b), "l"(c));
    return d;
}
__device__ __forceinline__ uint64_t pack_f32x2(float lo, float hi) {
    uint64_t d;
    asm("mov.b64 %0, {%1, %2};" : "=l"(d) : "f"(lo), "f"(hi));
    return d;
}
__device__ __forceinline__ void unpack_f32x2(float& lo, float& hi, uint64_t v) {
    asm("mov.b64 {%0, %1}, %2;" : "=f"(lo), "=f"(hi) : "l"(v));
}

// PDL device hooks (sm_90-baseline griddepcontrol, not arch-'a'-gated)
__device__ __forceinline__ void pdl_trigger() {
    asm volatile("griddepcontrol.launch_dependents;");
}
__device__ __forceinline__ void pdl_wait() {
    asm volatile("griddepcontrol.wait;" ::: "memory");
}

// ---------------------------------------------------------------------------
// Kernel 1 (fused prologue):
//   blocks [0, FILT_BLOCKS):  filters -> fp16 B' rows (R12-exact: FFMA2,
//                             p-unroll x4, float4 T loads, 4 j per thread)
//   blocks [FILT_BLOCKS, ..): convert 4 x-rows per block, 4 independent
//                             float4 loads per thread (MLP 4)
// ---------------------------------------------------------------------------
__global__ void __launch_bounds__(256)
prologue_kernel(const float* __restrict__ x,
                const float* __restrict__ params,
                const float* __restrict__ T) {
    if (blockIdx.x >= FILT_BLOCKS) {
        // ---- convert x: 4096 floats per block, 4 float4 per thread ----
        const int cb = blockIdx.x - FILT_BLOCKS;          // 0..1023
        const size_t base = (size_t)cb * 4096;
        float4 v[4];
#pragma unroll
        for (int q = 0; q < 4; q++)
            v[q] = *reinterpret_cast<const float4*>(x + base + q * 1024 + (threadIdx.x << 2));
#pragma unroll
        for (int q = 0; q < 4; q++) {
            ushort4 hv;
            hv.x = __half_as_ushort(__float2half_rn(v[q].x));
            hv.y = __half_as_ushort(__float2half_rn(v[q].y));
            hv.z = __half_as_ushort(__float2half_rn(v[q].z));
            hv.w = __half_as_ushort(__float2half_rn(v[q].w));
            *reinterpret_cast<ushort4*>(g_A + base + q * 1024 + (threadIdx.x << 2)) = hv;
        }
        pdl_trigger();
        return;
    }

    // ---- build filters (R12-exact) ----
    __shared__ __align__(8) uint64_t sp2[P_DIM * E_DIM];   // {w,w} packed
    for (int s = threadIdx.x; s < P_DIM * E_DIM; s += blockDim.x) {
        float w = params[s];
        sp2[s] = pack_f32x2(w, w);
    }
    __syncthreads();

    int t = blockIdx.x * blockDim.x + threadIdx.x;
    int idx4 = t << 2;
    int i = idx4 >> 10;
    int j = idx4 & (N_DIM - 1);

    uint64_t acc01[E_DIM], acc23[E_DIM];
    const uint64_t z = pack_f32x2(0.0f, 0.0f);
#pragma unroll
    for (int e = 0; e < E_DIM; e++) { acc01[e] = z; acc23[e] = z; }

#pragma unroll
    for (int p0 = 0; p0 < P_DIM; p0 += 4) {
        float4 tv0 = *reinterpret_cast<const float4*>(T + ((size_t)(p0+0) << 20) + idx4);
        float4 tv1 = *reinterpret_cast<const float4*>(T + ((size_t)(p0+1) << 20) + idx4);
        float4 tv2 = *reinterpret_cast<const float4*>(T + ((size_t)(p0+2) << 20) + idx4);
        float4 tv3 = *reinterpret_cast<const float4*>(T + ((size_t)(p0+3) << 20) + idx4);
        uint64_t t0a = pack_f32x2(tv0.x, tv0.y), t0b = pack_f32x2(tv0.z, tv0.w);
        uint64_t t1a = pack_f32x2(tv1.x, tv1.y), t1b = pack_f32x2(tv1.z, tv1.w);
        uint64_t t2a = pack_f32x2(tv2.x, tv2.y), t2b = pack_f32x2(tv2.z, tv2.w);
        uint64_t t3a = pack_f32x2(tv3.x, tv3.y), t3b = pack_f32x2(tv3.z, tv3.w);
#pragma unroll
        for (int e = 0; e < E_DIM; e++) {
            uint64_t w0 = sp2[(p0+0) * E_DIM + e];
            uint64_t w1 = sp2[(p0+1) * E_DIM + e];
            uint64_t w2 = sp2[(p0+2) * E_DIM + e];
            uint64_t w3 = sp2[(p0+3) * E_DIM + e];
            acc01[e] = fma_f32x2(t0a, w0, acc01[e]);
            acc23[e] = fma_f32x2(t0b, w0, acc23[e]);
            acc01[e] = fma_f32x2(t1a, w1, acc01[e]);
            acc23[e] = fma_f32x2(t1b, w1, acc23[e]);
            acc01[e] = fma_f32x2(t2a, w2, acc01[e]);
            acc23[e] = fma_f32x2(t2b, w2, acc23[e]);
            acc01[e] = fma_f32x2(t3a, w3, acc01[e]);
            acc23[e] = fma_f32x2(t3b, w3, acc23[e]);
        }
    }

#pragma unroll
    for (int e = 0; e < E_DIM; e++) {
        int c = i * E_DIM + e;
        float a0, a1, a2, a3;
        unpack_f32x2(a0, a1, acc01[e]);
        unpack_f32x2(a2, a3, acc23[e]);
        ushort4 hv;
        hv.x = __half_as_ushort(__float2half_rn(a0));
        hv.y = __half_as_ushort(__float2half_rn(a1));
        hv.z = __half_as_ushort(__float2half_rn(a2));
        hv.w = __half_as_ushort(__float2half_rn(a3));
        *reinterpret_cast<ushort4*>(g_Bm + (size_t)c * KDIM + j) = hv;
    }
    pdl_trigger();
}

// ---------------------------------------------------------------------------
// Kernel 2: GEMM out[b,c] = sum_k A[b,k]*W[c,k], swish, fp32 out.
// CTA 128x128, 8 warps (4Mx2N, 32x64 each), 3-stage cp.async pipeline,
// 2 CTAs/SM.  Byte-identical mainloop to the proven 332us version + PDL wait.
// ---------------------------------------------------------------------------
__device__ __forceinline__ void load_chunk(uint32_t sbase, int tid, int kc,
                                           const __half* __restrict__ Ag,
                                           const __half* __restrict__ Bg) {
    int st = kc % NSTAGES;
    uint32_t stA = sbase + st * STAGE_BYTES;
    uint32_t stB = stA + STAGE_A_BYTES;
    const __half* ga = Ag + kc * BK;
    const __half* gb = Bg + kc * BK;
#pragma unroll
    for (int i = 0; i < 4; i++) {               // A: 128 rows x 8 vec16
        int v = i * NTHREADS + tid;
        int row = v >> 3, c16 = v & 7;
        uint32_t off = (uint32_t)(row * 128 + c16 * 16);
        cp_async16(stA + sw128(off), ga + (size_t)row * KDIM + (c16 << 3));
    }
#pragma unroll
    for (int i = 0; i < 4; i++) {               // B: 128 rows x 8 vec16
        int v = i * NTHREADS + tid;
        int row = v >> 3, c16 = v & 7;
        uint32_t off = (uint32_t)(row * 128 + c16 * 16);
        cp_async16(stB + sw128(off), gb + (size_t)row * KDIM + (c16 << 3));
    }
    asm volatile("cp.async.commit_group;\n" ::: "memory");
}

__global__ void __launch_bounds__(NTHREADS, 2)
gemm_swish_kernel(float* __restrict__ out) {
    extern __shared__ char dsm[];
    const int tid  = threadIdx.x;
    const int wid  = tid >> 5;
    const int lane = tid & 31;
    const int warp_m = wid & 3;     // 0..3 -> 32-row slices
    const int warp_n = wid >> 2;    // 0..1 -> 64-col slices

    uint32_t sbase = cvta_shared(dsm);

    const size_t m_base = (size_t)blockIdx.x * BM;
    const size_t n_base = (size_t)blockIdx.y * BN;
    const __half* __restrict__ Ag = g_A  + m_base * KDIM;
    const __half* __restrict__ Bg = g_Bm + n_base * KDIM;

    float acc[2][8][4];
#pragma unroll
    for (int mi = 0; mi < 2; mi++)
#pragma unroll
        for (int ni = 0; ni < 8; ni++)
#pragma unroll
            for (int c = 0; c < 4; c++) acc[mi][ni][c] = 0.0f;

    // PDL: prologue grid must be complete before reading g_A/g_Bm.
    pdl_wait();

    // prologue: stages 0,1 in flight
    load_chunk(sbase, tid, 0, Ag, Bg);
    load_chunk(sbase, tid, 1, Ag, Bg);

    // per-lane ldmatrix row offsets
    const int a_row = warp_m * 32 + (lane & 15);                      // + mi*16
    const int a_kh  = (lane >> 4) << 4;                               // 0/16 B
    const int b_row = warp_n * 64 + (lane & 7) + ((lane & 16) >> 1);  // + ni*16
    const int b_kh  = (lane & 8) << 1;                                // 0/16 B

    for (int k = 0; k < NCH; k++) {
        if (k < NCH - 1) asm volatile("cp.async.wait_group 1;\n" ::: "memory");
        else             asm volatile("cp.async.wait_group 0;\n" ::: "memory");
        __syncthreads();

        if (k + 2 < NCH) load_chunk(sbase, tid, k + 2, Ag, Bg);

        int st = k % NSTAGES;
        uint32_t stA = sbase + st * STAGE_BYTES;
        uint32_t stB = stA + STAGE_A_BYTES;

#pragma unroll
        for (int kk = 0; kk < 4; kk++) {        // 4 x k16 per 64-chunk
            uint32_t b[4][4];
#pragma unroll
            for (int ni = 0; ni < 4; ni++) {
                uint32_t off = (uint32_t)((b_row + ni * 16) * 128 + kk * 32 + b_kh);
                ldmatrix_x4(b[ni], stB + sw128(off));
            }
            uint32_t a[2][4];
#pragma unroll
            for (int mi = 0; mi < 2; mi++) {
                uint32_t off = (uint32_t)((a_row + mi * 16) * 128 + kk * 32 + a_kh);
                ldmatrix_x4(a[mi], stA + sw128(off));
            }
#pragma unroll
            for (int mi = 0; mi < 2; mi++)
#pragma unroll
                for (int n8 = 0; n8 < 8; n8++)
                    mma_f16(acc[mi][n8], a[mi],
                            b[n8 >> 1][(n8 & 1) * 2],
                            b[n8 >> 1][(n8 & 1) * 2 + 1]);
        }
    }

    // epilogue: swish + store fp32
    const int quad = lane >> 2;        // 0..7: row within 8-row group
    const int tcol = (lane & 3) * 2;   // col pair
#pragma unroll
    for (int mi = 0; mi < 2; mi++) {
        size_t row0 = m_base + warp_m * 32 + mi * 16 + quad;
#pragma unroll
        for (int n8 = 0; n8 < 8; n8++) {
            size_t col = n_base + warp_n * 64 + n8 * 8 + tcol;
            float a0 = acc[mi][n8][0], a1 = acc[mi][n8][1];
            float a2 = acc[mi][n8][2], a3 = acc[mi][n8][3];
            float2 v0, v1;
            v0.x = a0 / (1.0f + __expf(-a0));
            v0.y = a1 / (1.0f + __expf(-a1));
            v1.x = a2 / (1.0f + __expf(-a2));
            v1.y = a3 / (1.0f + __expf(-a3));
            *reinterpret_cast<float2*>(out + row0 * C_DIM + col)       = v0;
            *reinterpret_cast<float2*>(out + (row0 + 8) * C_DIM + col) = v1;
        }
    }
}

// ---------------------------------------------------------------------------
// Launch: prologue, then GEMM with PDL (programmatic stream serialization)
// ---------------------------------------------------------------------------
extern "C" void kernel_launch(void* const* d_in, const int* in_sizes, int n_in,
                              void* d_out, int out_size) {
    const float* x = nullptr;
    const float* params = nullptr;
    const float* T = nullptr;
    for (int i = 0; i < n_in; i++) {
        if (in_sizes[i] == B_ROWS * N_DIM)             x      = (const float*)d_in[i];
        else if (in_sizes[i] == P_DIM * E_DIM)         params = (const float*)d_in[i];
        else if (in_sizes[i] == P_DIM * N_DIM * N_DIM) T      = (const float*)d_in[i];
    }
    float* out = (float*)d_out;

    prologue_kernel<<<FILT_BLOCKS + CONV_BLOCKS, 256>>>(x, params, T);

    cudaFuncSetAttribute(gemm_swish_kernel,
                         cudaFuncAttributeMaxDynamicSharedMemorySize, SMEM_DYN);

    cudaLaunchConfig_t cfg = {};
    cfg.gridDim = dim3(B_ROWS / BM, C_DIM / BN);
    cfg.blockDim = dim3(NTHREADS);
    cfg.dynamicSmemBytes = SMEM_DYN;
    cfg.stream = 0;
    cudaLaunchAttribute attrs[1];
    attrs[0].id = cudaLaunchAttributeProgrammaticStreamSerialization;
    attrs[0].val.programmaticStreamSerializationAllowed = 1;
    cfg.attrs = attrs;
    cfg.numAttrs = 1;
    cudaLaunchKernelEx(&cfg, gemm_swish_kernel, out);
}